// round 1
// baseline (speedup 1.0000x reference)
#include <cuda_runtime.h>
#include <cstdint>

// Problem constants
#define Bb   8
#define Lseq 8192
#define Hd   768
#define Mtot (Bb * Lseq)        // 65536
#define LAMK 0.1f

// ---------------- scratch (static device globals; no runtime alloc) ----------
__device__ float g_v[(size_t)Mtot * Hd];      // silu(x*D + conv), (M, H) row-major
__device__ int   g_tap_idx[Hd * Lseq];
__device__ float g_tap_val[Hd * Lseq];
__device__ int   g_tap_cnt[Hd];

// ---------------- helpers ----------------------------------------------------
__device__ __forceinline__ float sigmoidf_(float z) {
    return 1.0f / (1.0f + __expf(-z));
}

__device__ __forceinline__ unsigned f2tf32(float f) {
    unsigned u;
    asm("cvt.rna.tf32.f32 %0, %1;" : "=r"(u) : "f"(f));
    return u;
}

__device__ __forceinline__ void mma_tf32(float* d, const unsigned* a, const unsigned* b) {
    asm volatile(
        "mma.sync.aligned.m16n8k8.row.col.f32.tf32.tf32.f32 "
        "{%0,%1,%2,%3}, {%4,%5,%6,%7}, {%8,%9}, {%0,%1,%2,%3};\n"
        : "+f"(d[0]), "+f"(d[1]), "+f"(d[2]), "+f"(d[3])
        : "r"(a[0]), "r"(a[1]), "r"(a[2]), "r"(a[3]),
          "r"(b[0]), "r"(b[1]));
}

// ---------------- kernel 1: soft-threshold + ordered tap compaction ----------
// One warp per h. Ordered compaction via ballot prefix -> deterministic.
__global__ void build_taps_kernel(const float* __restrict__ kern) {
    int h = blockIdx.x;
    int lane = threadIdx.x;
    const float* kr = kern + (size_t)h * Lseq;
    int* ti = g_tap_idx + (size_t)h * Lseq;
    float* tv = g_tap_val + (size_t)h * Lseq;
    int cnt = 0;
    for (int base = 0; base < Lseq; base += 32) {
        float kv = kr[base + lane];
        float mag = fabsf(kv) - LAMK;
        bool p = mag > 0.0f;
        unsigned msk = __ballot_sync(0xffffffffu, p);
        if (p) {
            int pos = cnt + __popc(msk & ((1u << lane) - 1u));
            ti[pos] = base + lane;
            tv[pos] = copysignf(mag, kv);
        }
        cnt += __popc(msk);
    }
    if (lane == 0) g_tap_cnt[h] = cnt;
}

// ---------------- kernel 2: v = silu(x*D + sparse_causal_conv) ---------------
// m = b*L + l ; u[b,h,l] = x[b,l,h]. Fast path (cnt==0) is pure elementwise.
__global__ void prep_v_kernel(const float* __restrict__ x, const float* __restrict__ D) {
    const int H4 = Hd / 4;
    int i = blockIdx.x * blockDim.x + threadIdx.x;   // one float4 along H
    int m = i / H4;
    int h4 = (i - m * H4) * 4;

    float4 xv = *reinterpret_cast<const float4*>(x + (size_t)m * Hd + h4);
    float4 dv = *reinterpret_cast<const float4*>(D + h4);
    float s[4] = { xv.x * dv.x, xv.y * dv.y, xv.z * dv.z, xv.w * dv.w };

#pragma unroll
    for (int c = 0; c < 4; ++c) {
        int h = h4 + c;
        int cnt = g_tap_cnt[h];
        if (cnt > 0) {                       // only triggers if taps survive threshold
            int l = m & (Lseq - 1);
            int b = m >> 13;                 // L = 8192 = 2^13
            const int* ti = g_tap_idx + (size_t)h * Lseq;
            const float* tv = g_tap_val + (size_t)h * Lseq;
            float acc = 0.0f;
            for (int t = 0; t < cnt; ++t) {
                int j = ti[t];
                if (j <= l)
                    acc += tv[t] * x[((size_t)b * Lseq + (l - j)) * Hd + h];
            }
            s[c] += acc;
        }
    }

    float4 o;
    o.x = s[0] * sigmoidf_(s[0]);
    o.y = s[1] * sigmoidf_(s[1]);
    o.z = s[2] * sigmoidf_(s[2]);
    o.w = s[3] * sigmoidf_(s[3]);
    *reinterpret_cast<float4*>(g_v + (size_t)m * Hd + h4) = o;
}

// ---------------- kernel 3: fused GEMM(tf32) + bias + GLU + residual ---------
// z[m,n] = sum_k v[m,k] * W[n,k] (+b[n]);  out[m,h] = z_a*sigmoid(z_g) + x[m,h]
// CTA tile: 128 (M) x 64 (N-half) -> computes both a-half (W rows n0..) and
// g-half (W rows 768+n0..) so the GLU is fused in the epilogue.
#define BM 128
#define BN 64
#define BK 16
#define KTILES (Hd / BK)   // 48

__global__ __launch_bounds__(256, 1)
void gemm_glu_kernel(const float* __restrict__ W, const float* __restrict__ bias,
                     const float* __restrict__ x, float* __restrict__ out) {
    __shared__ unsigned As[2][BK][BM + 4];        // [k][m], tf32 bits
    __shared__ unsigned Bs[2][BK][2 * BN + 4];    // [k][n], n<64 = a-half, n>=64 = g-half

    const float* v = g_v;
    int tid  = threadIdx.x;
    int lane = tid & 31;
    int warp = tid >> 5;
    int wm = warp & 3;                 // 4 warps over M (32 rows each)
    int wn = warp >> 2;                // 2 warps over N-half (32 cols each)

    int m0 = blockIdx.x * BM;
    int n0 = blockIdx.y * BN;

    // global->smem loader mapping: 256 threads, each handles 2 rows x 1 float4
    int lrow = tid >> 2;               // 0..63
    int lkq  = (tid & 3) * 4;          // 0,4,8,12
    int arow0 = m0 + lrow;
    int arow1 = m0 + lrow + 64;
    int gn0 = n0 + lrow;               // a-half W row
    int gn1 = Hd + n0 + lrow;          // g-half W row

    float accA[2][4][4];
    float accG[2][4][4];
#pragma unroll
    for (int mi = 0; mi < 2; ++mi)
#pragma unroll
        for (int ni = 0; ni < 4; ++ni)
#pragma unroll
            for (int r = 0; r < 4; ++r) { accA[mi][ni][r] = 0.f; accG[mi][ni][r] = 0.f; }

    float4 pa0, pa1, pw0, pw1;

    // prologue: tile 0
    {
        int kt = 0;
        pa0 = *reinterpret_cast<const float4*>(v + (size_t)arow0 * Hd + kt + lkq);
        pa1 = *reinterpret_cast<const float4*>(v + (size_t)arow1 * Hd + kt + lkq);
        pw0 = *reinterpret_cast<const float4*>(W + (size_t)gn0 * Hd + kt + lkq);
        pw1 = *reinterpret_cast<const float4*>(W + (size_t)gn1 * Hd + kt + lkq);
        As[0][lkq + 0][lrow]      = f2tf32(pa0.x);
        As[0][lkq + 1][lrow]      = f2tf32(pa0.y);
        As[0][lkq + 2][lrow]      = f2tf32(pa0.z);
        As[0][lkq + 3][lrow]      = f2tf32(pa0.w);
        As[0][lkq + 0][lrow + 64] = f2tf32(pa1.x);
        As[0][lkq + 1][lrow + 64] = f2tf32(pa1.y);
        As[0][lkq + 2][lrow + 64] = f2tf32(pa1.z);
        As[0][lkq + 3][lrow + 64] = f2tf32(pa1.w);
        Bs[0][lkq + 0][lrow]      = f2tf32(pw0.x);
        Bs[0][lkq + 1][lrow]      = f2tf32(pw0.y);
        Bs[0][lkq + 2][lrow]      = f2tf32(pw0.z);
        Bs[0][lkq + 3][lrow]      = f2tf32(pw0.w);
        Bs[0][lkq + 0][lrow + 64] = f2tf32(pw1.x);
        Bs[0][lkq + 1][lrow + 64] = f2tf32(pw1.y);
        Bs[0][lkq + 2][lrow + 64] = f2tf32(pw1.z);
        Bs[0][lkq + 3][lrow + 64] = f2tf32(pw1.w);
    }
    __syncthreads();

    int rq = lane >> 2;        // 0..7
    int kq = lane & 3;         // 0..3

    for (int t = 0; t < KTILES; ++t) {
        int buf = t & 1;
        if (t + 1 < KTILES) {
            int kt = (t + 1) * BK;
            pa0 = *reinterpret_cast<const float4*>(v + (size_t)arow0 * Hd + kt + lkq);
            pa1 = *reinterpret_cast<const float4*>(v + (size_t)arow1 * Hd + kt + lkq);
            pw0 = *reinterpret_cast<const float4*>(W + (size_t)gn0 * Hd + kt + lkq);
            pw1 = *reinterpret_cast<const float4*>(W + (size_t)gn1 * Hd + kt + lkq);
        }

        // compute on buf
#pragma unroll
        for (int kk = 0; kk < BK; kk += 8) {
            unsigned af[2][4], bfa[4][2], bfg[4][2];
            int kc = kk + kq;
#pragma unroll
            for (int mi = 0; mi < 2; ++mi) {
                int mr = wm * 32 + mi * 16 + rq;
                af[mi][0] = As[buf][kc][mr];
                af[mi][1] = As[buf][kc][mr + 8];
                af[mi][2] = As[buf][kc + 4][mr];
                af[mi][3] = As[buf][kc + 4][mr + 8];
            }
#pragma unroll
            for (int ni = 0; ni < 4; ++ni) {
                int nc = wn * 32 + ni * 8 + rq;
                bfa[ni][0] = Bs[buf][kc][nc];
                bfa[ni][1] = Bs[buf][kc + 4][nc];
                bfg[ni][0] = Bs[buf][kc][64 + nc];
                bfg[ni][1] = Bs[buf][kc + 4][64 + nc];
            }
#pragma unroll
            for (int mi = 0; mi < 2; ++mi)
#pragma unroll
                for (int ni = 0; ni < 4; ++ni) {
                    mma_tf32(accA[mi][ni], af[mi], bfa[ni]);
                    mma_tf32(accG[mi][ni], af[mi], bfg[ni]);
                }
        }

        if (t + 1 < KTILES) {
            __syncthreads();
            int nb = buf ^ 1;
            As[nb][lkq + 0][lrow]      = f2tf32(pa0.x);
            As[nb][lkq + 1][lrow]      = f2tf32(pa0.y);
            As[nb][lkq + 2][lrow]      = f2tf32(pa0.z);
            As[nb][lkq + 3][lrow]      = f2tf32(pa0.w);
            As[nb][lkq + 0][lrow + 64] = f2tf32(pa1.x);
            As[nb][lkq + 1][lrow + 64] = f2tf32(pa1.y);
            As[nb][lkq + 2][lrow + 64] = f2tf32(pa1.z);
            As[nb][lkq + 3][lrow + 64] = f2tf32(pa1.w);
            Bs[nb][lkq + 0][lrow]      = f2tf32(pw0.x);
            Bs[nb][lkq + 1][lrow]      = f2tf32(pw0.y);
            Bs[nb][lkq + 2][lrow]      = f2tf32(pw0.z);
            Bs[nb][lkq + 3][lrow]      = f2tf32(pw0.w);
            Bs[nb][lkq + 0][lrow + 64] = f2tf32(pw1.x);
            Bs[nb][lkq + 1][lrow + 64] = f2tf32(pw1.y);
            Bs[nb][lkq + 2][lrow + 64] = f2tf32(pw1.z);
            Bs[nb][lkq + 3][lrow + 64] = f2tf32(pw1.w);
            __syncthreads();
        }
    }

    // epilogue: bias + GLU + residual, direct global stores
    int cq = (lane & 3) * 2;
#pragma unroll
    for (int mi = 0; mi < 2; ++mi) {
        int r0 = m0 + wm * 32 + mi * 16 + rq;
        int r1 = r0 + 8;
#pragma unroll
        for (int ni = 0; ni < 4; ++ni) {
            int col = n0 + wn * 32 + ni * 8 + cq;
            float ba0 = bias[col],      ba1 = bias[col + 1];
            float bg0 = bias[Hd + col], bg1 = bias[Hd + col + 1];

            float a00 = accA[mi][ni][0] + ba0, a01 = accA[mi][ni][1] + ba1;
            float g00 = accG[mi][ni][0] + bg0, g01 = accG[mi][ni][1] + bg1;
            float2 xr0 = *reinterpret_cast<const float2*>(x + (size_t)r0 * Hd + col);
            float2 o0;
            o0.x = a00 * sigmoidf_(g00) + xr0.x;
            o0.y = a01 * sigmoidf_(g01) + xr0.y;
            *reinterpret_cast<float2*>(out + (size_t)r0 * Hd + col) = o0;

            float a10 = accA[mi][ni][2] + ba0, a11 = accA[mi][ni][3] + ba1;
            float g10 = accG[mi][ni][2] + bg0, g11 = accG[mi][ni][3] + bg1;
            float2 xr1 = *reinterpret_cast<const float2*>(x + (size_t)r1 * Hd + col);
            float2 o1;
            o1.x = a10 * sigmoidf_(g10) + xr1.x;
            o1.y = a11 * sigmoidf_(g11) + xr1.y;
            *reinterpret_cast<float2*>(out + (size_t)r1 * Hd + col) = o1;
        }
    }
}

// ---------------- launch ------------------------------------------------------
extern "C" void kernel_launch(void* const* d_in, const int* in_sizes, int n_in,
                              void* d_out, int out_size) {
    const float* x    = (const float*)d_in[0];   // (8, 8192, 768)
    const float* kern = (const float*)d_in[1];   // (1, 768, 8192)
    const float* D    = (const float*)d_in[2];   // (1, 768)
    const float* W    = (const float*)d_in[3];   // (1536, 768)
    const float* bias = (const float*)d_in[4];   // (1536,)
    float* out = (float*)d_out;                  // (8, 8192, 768)

    build_taps_kernel<<<Hd, 32>>>(kern);

    int tot4 = Mtot * (Hd / 4);                  // 12,582,912
    prep_v_kernel<<<tot4 / 256, 256>>>(x, D);

    dim3 grid(Mtot / BM, Hd / BN);               // (512, 12)
    gemm_glu_kernel<<<grid, 256>>>(W, bias, x, out);
}

// round 3
// speedup vs baseline: 3.8428x; 3.8428x over previous
#include <cuda_runtime.h>
#include <cuda_fp16.h>
#include <cstdint>

// Problem constants
#define Bb   8
#define Lseq 8192
#define Hd   768
#define Mtot (Bb * Lseq)        // 65536
#define LAMK 0.1f

// GEMM tiling (fp16 mma.sync path)
#define KT    24                // K chunks of 32
#define RSB   80                // smem row stride bytes (40 halves) -> conflict-free ldmatrix
#define ATILE 10240             // 128 rows * 80B
#define STG   20480             // A tile + B tile per stage
#define NSTG  4
#define GSM   (NSTG * STG)      // 81920 bytes dynamic smem

// ---------------- scratch ----------------------------------------------------
__device__ __half g_vh[(size_t)Mtot * Hd];      // silu(x*D + conv) in fp16
__device__ __half g_wh[2 * Hd * Hd];            // W in fp16 (1536 x 768)
__device__ int    g_tap_idx[Hd * Lseq];
__device__ float  g_tap_val[Hd * Lseq];
__device__ int    g_tap_cnt[Hd];

// ---------------- helpers ----------------------------------------------------
__device__ __forceinline__ float sigmoidf_(float z) {
    return 1.0f / (1.0f + __expf(-z));
}

__device__ __forceinline__ uint32_t s2u(const void* p) {
    uint32_t a;
    asm("{ .reg .u64 t; cvta.to.shared.u64 t, %1; cvt.u32.u64 %0, t; }"
        : "=r"(a) : "l"(p));
    return a;
}

__device__ __forceinline__ void cp16(uint32_t dst, const void* src) {
    asm volatile("cp.async.cg.shared.global [%0], [%1], 16;\n"
                 :: "r"(dst), "l"(src));
}

__device__ __forceinline__ void ldsm4(uint32_t* r, uint32_t addr) {
    asm volatile("ldmatrix.sync.aligned.m8n8.x4.shared.b16 {%0,%1,%2,%3}, [%4];"
                 : "=r"(r[0]), "=r"(r[1]), "=r"(r[2]), "=r"(r[3]) : "r"(addr));
}

__device__ __forceinline__ void mma16816(float* d, const uint32_t* a,
                                         uint32_t b0, uint32_t b1) {
    asm volatile(
        "mma.sync.aligned.m16n8k16.row.col.f32.f16.f16.f32 "
        "{%0,%1,%2,%3}, {%4,%5,%6,%7}, {%8,%9}, {%0,%1,%2,%3};\n"
        : "+f"(d[0]), "+f"(d[1]), "+f"(d[2]), "+f"(d[3])
        : "r"(a[0]), "r"(a[1]), "r"(a[2]), "r"(a[3]), "r"(b0), "r"(b1));
}

// ---------------- kernel 0: W fp32 -> fp16 -----------------------------------
__global__ void wconv_kernel(const float* __restrict__ W) {
    int i = blockIdx.x * 256 + threadIdx.x;        // 1536*768 / 256 blocks
    g_wh[i] = __float2half_rn(W[i]);
}

// ---------------- kernel 1: soft-threshold + ordered tap compaction ----------
__global__ void build_taps_kernel(const float* __restrict__ kern) {
    int h = blockIdx.x * 8 + (threadIdx.x >> 5);
    int lane = threadIdx.x & 31;
    const float* kr = kern + (size_t)h * Lseq;
    int* ti = g_tap_idx + (size_t)h * Lseq;
    float* tv = g_tap_val + (size_t)h * Lseq;
    int cnt = 0;
    for (int base = 0; base < Lseq; base += 32) {
        float kv = kr[base + lane];
        float mag = fabsf(kv) - LAMK;
        bool p = mag > 0.0f;
        unsigned msk = __ballot_sync(0xffffffffu, p);
        if (p) {
            int pos = cnt + __popc(msk & ((1u << lane) - 1u));
            ti[pos] = base + lane;
            tv[pos] = copysignf(mag, kv);
        }
        cnt += __popc(msk);
    }
    if (lane == 0) g_tap_cnt[h] = cnt;
}

// ---------------- kernel 2: v = silu(x*D + sparse_causal_conv) -> fp16 -------
__global__ void prep_v_kernel(const float* __restrict__ x, const float* __restrict__ D) {
    const int H4 = Hd / 4;
    int i = blockIdx.x * blockDim.x + threadIdx.x;
    int m = i / H4;
    int h4 = (i - m * H4) * 4;

    float4 xv = *reinterpret_cast<const float4*>(x + (size_t)m * Hd + h4);
    float4 dv = *reinterpret_cast<const float4*>(D + h4);
    float s[4] = { xv.x * dv.x, xv.y * dv.y, xv.z * dv.z, xv.w * dv.w };

#pragma unroll
    for (int c = 0; c < 4; ++c) {
        int h = h4 + c;
        int cnt = g_tap_cnt[h];
        if (cnt > 0) {                         // cold path (taps survive threshold)
            int l = m & (Lseq - 1);
            int b = m >> 13;
            const int* ti = g_tap_idx + (size_t)h * Lseq;
            const float* tv = g_tap_val + (size_t)h * Lseq;
            float acc = 0.0f;
            for (int t = 0; t < cnt; ++t) {
                int j = ti[t];
                if (j <= l)
                    acc += tv[t] * x[((size_t)b * Lseq + (l - j)) * Hd + h];
            }
            s[c] += acc;
        }
    }

    __half2 h01 = __floats2half2_rn(s[0] * sigmoidf_(s[0]), s[1] * sigmoidf_(s[1]));
    __half2 h23 = __floats2half2_rn(s[2] * sigmoidf_(s[2]), s[3] * sigmoidf_(s[3]));
    uint2 pk;
    pk.x = *reinterpret_cast<uint32_t*>(&h01);
    pk.y = *reinterpret_cast<uint32_t*>(&h23);
    *reinterpret_cast<uint2*>(g_vh + (size_t)m * Hd + h4) = pk;
}

// ---------------- kernel 3: fp16 mma GEMM + bias + GLU + residual ------------
// CTA: 128 M-rows x (64 a-cols + matching 64 g-cols). B smem rows 0..63 = W row
// n0+r, rows 64..127 = W row 768+n0+r. GLU fused in epilogue.
__global__ void __launch_bounds__(256, 2)
gemm_fp16_kernel(const float* __restrict__ bias, const float* __restrict__ x,
                 float* __restrict__ out) {
    extern __shared__ char dsm[];
    uint32_t sb = s2u(dsm);
    const int tid  = threadIdx.x;
    const int lane = tid & 31;
    const int warp = tid >> 5;
    const int wm = warp >> 2;            // 0..1 -> 64 M-rows each
    const int wn = warp & 3;             // 0..3 -> 16 a-cols (+16 g-cols) each
    const int m0 = blockIdx.y * 128;
    const int n0 = blockIdx.x * 64;

    // global->smem loader mapping: each thread owns 2 A units + 2 B units/stage
    const int i0 = tid, i1 = tid + 256;
    const int ar0 = i0 >> 2, au0 = i0 & 3;
    const int ar1 = i1 >> 2, au1 = i1 & 3;
    const __half* asrc0 = g_vh + (size_t)(m0 + ar0) * Hd + au0 * 8;
    const __half* asrc1 = g_vh + (size_t)(m0 + ar1) * Hd + au1 * 8;
    const int wr0 = (ar0 < 64) ? (n0 + ar0) : (704 + n0 + ar0);
    const int wr1 = (ar1 < 64) ? (n0 + ar1) : (704 + n0 + ar1);
    const __half* bsrc0 = g_wh + (size_t)wr0 * Hd + au0 * 8;
    const __half* bsrc1 = g_wh + (size_t)wr1 * Hd + au1 * 8;
    const uint32_t ad0 = (uint32_t)(ar0 * RSB + au0 * 16);
    const uint32_t ad1 = (uint32_t)(ar1 * RSB + au1 * 16);

    // prologue: stages 0..2
#pragma unroll
    for (int s = 0; s < 3; ++s) {
        uint32_t st = sb + s * STG;
        cp16(st + ad0, asrc0 + s * 32);
        cp16(st + ad1, asrc1 + s * 32);
        cp16(st + ATILE + ad0, bsrc0 + s * 32);
        cp16(st + ATILE + ad1, bsrc1 + s * 32);
        asm volatile("cp.async.commit_group;" ::: "memory");
    }

    // ldmatrix per-lane offsets
    const int lro = (lane & 7) + ((lane >> 3) & 1) * 8;
    const int lu  = lane >> 4;
    uint32_t aoff[4], boff[2];
#pragma unroll
    for (int mi = 0; mi < 4; ++mi)
        aoff[mi] = (uint32_t)((wm * 64 + mi * 16 + lro) * RSB + lu * 16);
    boff[0] = (uint32_t)((wn * 16 + lro) * RSB + lu * 16);
    boff[1] = (uint32_t)((64 + wn * 16 + lro) * RSB + lu * 16);

    float accA[4][2][4], accG[4][2][4];
#pragma unroll
    for (int mi = 0; mi < 4; ++mi)
#pragma unroll
        for (int nj = 0; nj < 2; ++nj)
#pragma unroll
            for (int r = 0; r < 4; ++r) { accA[mi][nj][r] = 0.f; accG[mi][nj][r] = 0.f; }

    for (int t = 0; t < KT; ++t) {
        asm volatile("cp.async.wait_group 2;" ::: "memory");
        __syncthreads();

        if (t + 3 < KT) {
            uint32_t st = sb + ((t + 3) & 3) * STG;
            int kw = (t + 3) * 32;
            cp16(st + ad0, asrc0 + kw);
            cp16(st + ad1, asrc1 + kw);
            cp16(st + ATILE + ad0, bsrc0 + kw);
            cp16(st + ATILE + ad1, bsrc1 + kw);
        }
        asm volatile("cp.async.commit_group;" ::: "memory");

        uint32_t ab = sb + (t & 3) * STG;
        uint32_t bb = ab + ATILE;
#pragma unroll
        for (int ks = 0; ks < 2; ++ks) {
            uint32_t kadd = (uint32_t)(ks * 32);   // 16 halves = 32B
            uint32_t afr[4][4];
#pragma unroll
            for (int mi = 0; mi < 4; ++mi)
                ldsm4(afr[mi], ab + aoff[mi] + kadd);
            uint32_t ba[4], bg[4];
            ldsm4(ba, bb + boff[0] + kadd);
            ldsm4(bg, bb + boff[1] + kadd);
#pragma unroll
            for (int mi = 0; mi < 4; ++mi) {
                mma16816(accA[mi][0], afr[mi], ba[0], ba[2]);
                mma16816(accA[mi][1], afr[mi], ba[1], ba[3]);
                mma16816(accG[mi][0], afr[mi], bg[0], bg[2]);
                mma16816(accG[mi][1], afr[mi], bg[1], bg[3]);
            }
        }
    }

    // epilogue: bias + GLU + residual
    const int r  = lane >> 2;
    const int c2 = (lane & 3) * 2;
#pragma unroll
    for (int nj = 0; nj < 2; ++nj) {
        int col = n0 + wn * 16 + nj * 8 + c2;
        float ba0 = __ldg(bias + col),      ba1 = __ldg(bias + col + 1);
        float bg0 = __ldg(bias + Hd + col), bg1 = __ldg(bias + Hd + col + 1);
#pragma unroll
        for (int mi = 0; mi < 4; ++mi) {
            int mrow = m0 + wm * 64 + mi * 16 + r;
            {
                float a0 = accA[mi][nj][0] + ba0, a1 = accA[mi][nj][1] + ba1;
                float g0 = accG[mi][nj][0] + bg0, g1 = accG[mi][nj][1] + bg1;
                float2 xv = __ldg(reinterpret_cast<const float2*>(x + (size_t)mrow * Hd + col));
                float2 o;
                o.x = a0 * sigmoidf_(g0) + xv.x;
                o.y = a1 * sigmoidf_(g1) + xv.y;
                *reinterpret_cast<float2*>(out + (size_t)mrow * Hd + col) = o;
            }
            {
                int mr2 = mrow + 8;
                float a0 = accA[mi][nj][2] + ba0, a1 = accA[mi][nj][3] + ba1;
                float g0 = accG[mi][nj][2] + bg0, g1 = accG[mi][nj][3] + bg1;
                float2 xv = __ldg(reinterpret_cast<const float2*>(x + (size_t)mr2 * Hd + col));
                float2 o;
                o.x = a0 * sigmoidf_(g0) + xv.x;
                o.y = a1 * sigmoidf_(g1) + xv.y;
                *reinterpret_cast<float2*>(out + (size_t)mr2 * Hd + col) = o;
            }
        }
    }
}

// ---------------- launch ------------------------------------------------------
extern "C" void kernel_launch(void* const* d_in, const int* in_sizes, int n_in,
                              void* d_out, int out_size) {
    const float* x    = (const float*)d_in[0];   // (8, 8192, 768)
    const float* kern = (const float*)d_in[1];   // (1, 768, 8192)
    const float* D    = (const float*)d_in[2];   // (1, 768)
    const float* W    = (const float*)d_in[3];   // (1536, 768)
    const float* bias = (const float*)d_in[4];   // (1536,)
    float* out = (float*)d_out;                  // (8, 8192, 768)

    cudaFuncSetAttribute(gemm_fp16_kernel,
                         cudaFuncAttributeMaxDynamicSharedMemorySize, GSM);

    wconv_kernel<<<(2 * Hd * Hd) / 256, 256>>>(W);
    build_taps_kernel<<<Hd / 8, 256>>>(kern);

    int tot4 = Mtot * (Hd / 4);
    prep_v_kernel<<<tot4 / 256, 256>>>(x, D);

    dim3 grid(Hd / 64, Mtot / 128);              // (12, 512)
    gemm_fp16_kernel<<<grid, 256, GSM>>>(bias, x, out);
}